// round 1
// baseline (speedup 1.0000x reference)
#include <cuda_runtime.h>

#define NUM_U 50000
#define NUM_I 50000
#define NE    1000000
#define DD    64

// ---------------- device scratch (static, allocation-free) ----------------
__device__ float g_qu1[NUM_U * DD];
__device__ float g_qi1[NUM_I * DD];
__device__ float g_oku[NUM_U * DD];
__device__ float g_oki[NUM_I * DD];
__device__ float g_pa_u[NUM_U], g_pb_u[NUM_U];
__device__ float g_pa_i[NUM_I], g_pb_i[NUM_I];
__device__ int   g_cnt_i[NUM_I], g_cnt_u[NUM_U];
__device__ int   g_cur_i[NUM_I], g_cur_u[NUM_U];
__device__ int   g_rp_i[NUM_I + 1], g_rp_u[NUM_U + 1];
__device__ int   g_col_i[NE];  // per item: neighbor user ids
__device__ int   g_col_u[NE];  // per user: neighbor item ids

// ---------------- CSR build ----------------
__global__ void k_zero_counts() {
    int i = blockIdx.x * blockDim.x + threadIdx.x;
    if (i < NUM_U) g_cnt_u[i] = 0;
    if (i < NUM_I) g_cnt_i[i] = 0;
}

__global__ void k_hist(const int* __restrict__ src, const int* __restrict__ dst) {
    int e = blockIdx.x * blockDim.x + threadIdx.x;
    if (e < NE) {
        atomicAdd(&g_cnt_i[dst[e]], 1);
        atomicAdd(&g_cnt_u[src[e]], 1);
    }
}

__global__ void k_scan() {
    // blockIdx.x: 0 -> items, 1 -> users
    const int n   = blockIdx.x ? NUM_U : NUM_I;
    int* cnt      = blockIdx.x ? g_cnt_u : g_cnt_i;
    int* cur      = blockIdx.x ? g_cur_u : g_cur_i;
    int* rp       = blockIdx.x ? g_rp_u  : g_rp_i;
    __shared__ int ssum[1024];
    int t = threadIdx.x;
    int C = (n + 1023) / 1024;
    int b = t * C;
    int e = min(n, b + C);
    int s = 0;
    for (int i = b; i < e; i++) s += cnt[i];
    ssum[t] = s;
    __syncthreads();
    for (int off = 1; off < 1024; off <<= 1) {
        int v = (t >= off) ? ssum[t - off] : 0;
        __syncthreads();
        ssum[t] += v;
        __syncthreads();
    }
    int run = ssum[t] - s;  // exclusive prefix at b
    for (int i = b; i < e; i++) {
        rp[i]  = run;
        cur[i] = run;
        run += cnt[i];
    }
    if (t == 1023) rp[n] = ssum[1023];
}

__global__ void k_scatter(const int* __restrict__ src, const int* __restrict__ dst) {
    int e = blockIdx.x * blockDim.x + threadIdx.x;
    if (e < NE) {
        int s = src[e], d = dst[e];
        int p = atomicAdd(&g_cur_i[d], 1);
        g_col_i[p] = s;
        int q = atomicAdd(&g_cur_u[s], 1);
        g_col_u[q] = d;
    }
}

// ---------------- per-node attention projections ----------------
// pa[n] = q[n] . Watt[0:64]   (src-role half)
// pb[n] = q[n] . Watt[64:128] (dst-role half)
__global__ void k_nodeproj(const float* __restrict__ q, const float* __restrict__ watt,
                           float* __restrict__ pa, float* __restrict__ pb, int n) {
    int gw    = (blockIdx.x * blockDim.x + threadIdx.x) >> 5;
    int lane  = threadIdx.x & 31;
    int nwarp = (gridDim.x * blockDim.x) >> 5;
    float2 wa = reinterpret_cast<const float2*>(watt)[lane];
    float2 wb = reinterpret_cast<const float2*>(watt)[32 + lane];
    for (int nd = gw; nd < n; nd += nwarp) {
        float2 qv = reinterpret_cast<const float2*>(q)[nd * 32 + lane];
        float da = qv.x * wa.x + qv.y * wa.y;
        float db = qv.x * wb.x + qv.y * wb.y;
        #pragma unroll
        for (int o = 16; o; o >>= 1) {
            da += __shfl_xor_sync(0xffffffffu, da, o);
            db += __shfl_xor_sync(0xffffffffu, db, o);
        }
        if (lane == 0) { pa[nd] = da; pb[nd] = db; }
    }
}

// ---------------- fused softmax-attention aggregation ----------------
// OK[node] = (sum_e exp(sigmoid(pa[nbr]+pb[node])) * feat[nbr]) / (sum_e exp(...))
__global__ void __launch_bounds__(256) k_agg(
    const float* __restrict__ feat, const float* __restrict__ pa,
    const float* __restrict__ pb, const int* __restrict__ rp,
    const int* __restrict__ col, float* __restrict__ ok, int n) {

    int warp = (blockIdx.x * blockDim.x + threadIdx.x) >> 5;
    int lane = threadIdx.x & 31;
    if (warp >= n) return;

    int beg = rp[warp];
    int end = rp[warp + 1];
    float pbn = pb[warp];
    float ax = 0.f, ay = 0.f, ssum = 0.f;
    const float2* f2 = reinterpret_cast<const float2*>(feat);

    for (int base = beg; base < end; base += 32) {
        int j = base + lane;
        float w = 0.f;
        int nbr = 0;
        if (j < end) {
            nbr = col[j];
            float x  = pa[nbr] + pbn;
            float sg = __fdividef(1.f, 1.f + __expf(-x));
            w = __expf(sg);
        }
        ssum += w;
        int cnt = min(32, end - base);
        #pragma unroll 4
        for (int t = 0; t < cnt; t++) {
            float wt = __shfl_sync(0xffffffffu, w, t);
            int   nb = __shfl_sync(0xffffffffu, nbr, t);
            float2 v = f2[nb * 32 + lane];
            ax = fmaf(wt, v.x, ax);
            ay = fmaf(wt, v.y, ay);
        }
    }
    #pragma unroll
    for (int o = 16; o; o >>= 1) ssum += __shfl_xor_sync(0xffffffffu, ssum, o);
    float inv = (end > beg) ? __fdividef(1.f, fmaxf(ssum, 1e-12f)) : 0.f;
    ok[warp * 64 + 2 * lane]     = ax * inv;
    ok[warp * 64 + 2 * lane + 1] = ay * inv;
}

// ---------------- layer-1 update: out = (q + ok) @ W.T  (64x64) ----------------
__global__ void __launch_bounds__(256) k_update(
    const float* __restrict__ q, const float* __restrict__ okk,
    const float* __restrict__ W, float* __restrict__ out, int n) {

    __shared__ float Wt[64 * 65];   // Wt[k*65+j] = W[j*64+k]
    __shared__ float sx[8][64];
    int tid = threadIdx.x;
    for (int idx = tid; idx < 4096; idx += 256) {
        int j = idx >> 6, k = idx & 63;
        Wt[k * 65 + j] = W[idx];
    }
    __syncthreads();

    int w = tid >> 5, lane = tid & 31;
    int nwarp = (gridDim.x * blockDim.x) >> 5;
    for (int nd = (blockIdx.x * 256 + tid) >> 5; nd < n; nd += nwarp) {
        float2 qv = reinterpret_cast<const float2*>(q)[nd * 32 + lane];
        float2 ov = reinterpret_cast<const float2*>(okk)[nd * 32 + lane];
        sx[w][2 * lane]     = qv.x + ov.x;
        sx[w][2 * lane + 1] = qv.y + ov.y;
        __syncwarp();
        float a0 = 0.f, a1 = 0.f;
        #pragma unroll
        for (int k = 0; k < 64; k++) {
            float xv = sx[w][k];
            a0 = fmaf(xv, Wt[k * 65 + lane], a0);
            a1 = fmaf(xv, Wt[k * 65 + 32 + lane], a1);
        }
        out[nd * 64 + lane]      = a0;
        out[nd * 64 + 32 + lane] = a1;
        __syncwarp();
    }
}

// ---------------- fused layer-2 update + OV + fc + output concat ----------------
__global__ void __launch_bounds__(128) k_final(
    const float* __restrict__ q1, const float* __restrict__ ok2,
    const int* __restrict__ rp, const float* __restrict__ Eemb,
    const float* __restrict__ Wupd2, const float* __restrict__ WV2,
    const float* __restrict__ bV2, const float* __restrict__ Wfc,
    const float* __restrict__ bfc, float* __restrict__ outp, int n) {

    __shared__ float W2t[64 * 17];  // [k][j], j<16
    __shared__ float WVt[64 * 17];
    __shared__ float Wft[32 * 65];  // [k][j], j<64
    __shared__ float sx[4][64], sk[4][64], hv[4][32];
    __shared__ float sb2[16], sbf[64];
    int tid = threadIdx.x;
    for (int idx = tid; idx < 1024; idx += 128) {
        int j = idx >> 6, k = idx & 63;
        W2t[k * 17 + j] = Wupd2[idx];
        WVt[k * 17 + j] = WV2[idx];
    }
    for (int idx = tid; idx < 2048; idx += 128) {
        int j = idx >> 5, k = idx & 31;
        Wft[k * 65 + j] = Wfc[idx];
    }
    if (tid < 16) sb2[tid] = bV2[tid];
    if (tid < 64) sbf[tid] = bfc[tid];
    __syncthreads();

    int w = tid >> 5, lane = tid & 31;
    int nwarp = (gridDim.x * blockDim.x) >> 5;
    for (int nd = (blockIdx.x * 128 + tid) >> 5; nd < n; nd += nwarp) {
        float2 qv = reinterpret_cast<const float2*>(q1)[nd * 32 + lane];
        float2 ov = reinterpret_cast<const float2*>(ok2)[nd * 32 + lane];
        sk[w][2 * lane]     = ov.x;
        sk[w][2 * lane + 1] = ov.y;
        sx[w][2 * lane]     = qv.x + ov.x;
        sx[w][2 * lane + 1] = qv.y + ov.y;
        __syncwarp();

        float sflag = (rp[nd + 1] > rp[nd]) ? 1.f : 0.f;
        float acc;
        if (lane < 16) {
            acc = 0.f;
            #pragma unroll
            for (int k = 0; k < 64; k++) acc = fmaf(sx[w][k], W2t[k * 17 + lane], acc);
        } else {
            int j = lane - 16;
            acc = sb2[j] * sflag;
            #pragma unroll
            for (int k = 0; k < 64; k++) acc = fmaf(sk[w][k], WVt[k * 17 + j], acc);
        }
        hv[w][lane] = acc;
        __syncwarp();

        float g0 = sbf[lane], g1 = sbf[lane + 32];
        #pragma unroll
        for (int k = 0; k < 32; k++) {
            float c = hv[w][k];
            g0 = fmaf(c, Wft[k * 65 + lane], g0);
            g1 = fmaf(c, Wft[k * 65 + 32 + lane], g1);
        }
        g0 = fmaxf(g0, 0.f);
        g1 = fmaxf(g1, 0.f);

        float2 ev = reinterpret_cast<const float2*>(Eemb)[nd * 32 + lane];
        float* orow = outp + (size_t)nd * 128;
        orow[2 * lane]     = ev.x;
        orow[2 * lane + 1] = ev.y;
        orow[64 + lane] = g0;
        orow[96 + lane] = g1;
        __syncwarp();
    }
}

// ---------------- host launcher ----------------
extern "C" void kernel_launch(void* const* d_in, const int* in_sizes, int n_in,
                              void* d_out, int out_size) {
    const float* E_u   = (const float*)d_in[0];
    const float* E_i   = (const float*)d_in[1];
    const float* Q_u   = (const float*)d_in[2];
    const float* Q_i   = (const float*)d_in[3];
    const float* Watt1 = (const float*)d_in[4];
    const float* Wupd1 = (const float*)d_in[5];
    const float* Watt2 = (const float*)d_in[8];
    const float* Wupd2 = (const float*)d_in[9];
    const float* WV2   = (const float*)d_in[10];
    const float* bV2   = (const float*)d_in[11];
    const float* Wfc   = (const float*)d_in[12];
    const float* bfc   = (const float*)d_in[13];
    const int*   src   = (const int*)d_in[14];
    const int*   dst   = (const int*)d_in[15];
    float* out = (float*)d_out;

    float *qu1, *qi1, *oku, *oki, *pau, *pbu, *pai, *pbi;
    int *rpi, *rpu, *coli, *colu;
    cudaGetSymbolAddress((void**)&qu1,  g_qu1);
    cudaGetSymbolAddress((void**)&qi1,  g_qi1);
    cudaGetSymbolAddress((void**)&oku,  g_oku);
    cudaGetSymbolAddress((void**)&oki,  g_oki);
    cudaGetSymbolAddress((void**)&pau,  g_pa_u);
    cudaGetSymbolAddress((void**)&pbu,  g_pb_u);
    cudaGetSymbolAddress((void**)&pai,  g_pa_i);
    cudaGetSymbolAddress((void**)&pbi,  g_pb_i);
    cudaGetSymbolAddress((void**)&rpi,  g_rp_i);
    cudaGetSymbolAddress((void**)&rpu,  g_rp_u);
    cudaGetSymbolAddress((void**)&coli, g_col_i);
    cudaGetSymbolAddress((void**)&colu, g_col_u);

    const int TE = 256;
    const int GE = (NE + TE - 1) / TE;

    // CSR build (graph is identical for both layers)
    k_zero_counts<<<(NUM_U + 255) / 256, 256>>>();
    k_hist<<<GE, TE>>>(src, dst);
    k_scan<<<2, 1024>>>();
    k_scatter<<<GE, TE>>>(src, dst);

    // ---- layer 1 ----
    k_nodeproj<<<592, 256>>>(Q_u, Watt1, pau, pbu, NUM_U);
    k_nodeproj<<<592, 256>>>(Q_i, Watt1, pai, pbi, NUM_I);
    k_agg<<<(NUM_I + 7) / 8, 256>>>(Q_u, pau, pbi, rpi, coli, oki, NUM_I);
    k_agg<<<(NUM_U + 7) / 8, 256>>>(Q_i, pai, pbu, rpu, colu, oku, NUM_U);
    k_update<<<1184, 256>>>(Q_u, oku, Wupd1, qu1, NUM_U);
    k_update<<<1184, 256>>>(Q_i, oki, Wupd1, qi1, NUM_I);

    // ---- layer 2 ----
    k_nodeproj<<<592, 256>>>(qu1, Watt2, pau, pbu, NUM_U);
    k_nodeproj<<<592, 256>>>(qi1, Watt2, pai, pbi, NUM_I);
    k_agg<<<(NUM_I + 7) / 8, 256>>>(qu1, pau, pbi, rpi, coli, oki, NUM_I);
    k_agg<<<(NUM_U + 7) / 8, 256>>>(qi1, pai, pbu, rpu, colu, oku, NUM_U);

    // ---- fused epilogue: layer-2 update + OV(=OK@Wv+b*s) + fc + concat ----
    k_final<<<2368, 128>>>(qu1, oku, rpu, E_u, Wupd2, WV2, bV2, Wfc, bfc,
                           out, NUM_U);
    k_final<<<2368, 128>>>(qi1, oki, rpi, E_i, Wupd2, WV2, bV2, Wfc, bfc,
                           out + (size_t)NUM_U * 128, NUM_I);
}